// round 1
// baseline (speedup 1.0000x reference)
#include <cuda_runtime.h>
#include <cuda_bf16.h>
#include <math.h>

// Problem constants (from reference)
#define H_NF 128
#define N_GAUSS 50
#define CUTOFF 10.0f

// Gaussian smearing constants: offset = linspace(0, 10, 50), step = 10/49
// coeff = -0.5 / step^2
__device__ __forceinline__ float gauss_step() { return 10.0f / 49.0f; }

// ---------------------------------------------------------------------------
// Kernel 1: node embedding gather. One warp per node, float4 per lane.
// out row = 128 floats = 32 float4 (one per lane). Weight table 100x128
// floats = 51.2 KB -> L1 resident.
// ---------------------------------------------------------------------------
__global__ void node_emb_kernel(const int* __restrict__ atomic_ns,
                                const float4* __restrict__ weight4,
                                float4* __restrict__ out4,
                                int n_nodes) {
    int gtid = blockIdx.x * blockDim.x + threadIdx.x;
    int node = gtid >> 5;
    int lane = gtid & 31;
    if (node >= n_nodes) return;
    int a = __ldg(&atomic_ns[node]);               // warp-broadcast load
    out4[(size_t)node * 32 + lane] = __ldg(&weight4[(size_t)a * 32 + lane]);
}

// ---------------------------------------------------------------------------
// Kernel 2: edge distances + gaussian smearing.
// Block handles EPB edges. Phase 1: first EPB threads compute dist, write
// edge_weights (coalesced), store dist to smem. Phase 2: all threads write
// edge_embs as float2 (row stride 200 B, 8B-aligned) -> contiguous writes.
// ---------------------------------------------------------------------------
#define EPB 128
#define TPB 256

__global__ __launch_bounds__(TPB) void edge_kernel(
    const int* __restrict__ edge_index,   // [2, E]
    const float* __restrict__ coords,     // [N, 3]
    float2* __restrict__ edge_embs2,      // [E, 25] as float2
    float* __restrict__ edge_w,           // [E]
    long long n_edges) {
    __shared__ float s_dist[EPB];

    const long long e0 = (long long)blockIdx.x * EPB;
    const float step = gauss_step();
    const float coeff = -0.5f / (step * step);

    // Phase 1: distances
    if (threadIdx.x < EPB) {
        long long e = e0 + threadIdx.x;
        if (e < n_edges) {
            int i = __ldg(&edge_index[e]);
            int j = __ldg(&edge_index[n_edges + e]);
            float ax = __ldg(&coords[(size_t)i * 3 + 0]);
            float ay = __ldg(&coords[(size_t)i * 3 + 1]);
            float az = __ldg(&coords[(size_t)i * 3 + 2]);
            float bx = __ldg(&coords[(size_t)j * 3 + 0]);
            float by = __ldg(&coords[(size_t)j * 3 + 1]);
            float bz = __ldg(&coords[(size_t)j * 3 + 2]);
            float dx = ax - bx, dy = ay - by, dz = az - bz;
            float dist = sqrtf(fmaf(dx, dx, fmaf(dy, dy, dz * dz)));
            s_dist[threadIdx.x] = dist;
            edge_w[e] = dist;
        }
    }
    __syncthreads();

    // Phase 2: gaussian smearing, float2 stores. EPB*25 = 3200 float2 per blk.
    const int total = EPB * (N_GAUSS / 2);  // 3200
    #pragma unroll 4
    for (int k = threadIdx.x; k < total; k += TPB) {
        int le = k / (N_GAUSS / 2);          // local edge
        int p  = k - le * (N_GAUSS / 2);     // pair index 0..24
        long long e = e0 + le;
        if (e < n_edges) {
            float dist = s_dist[le];
            float d0 = dist - (float)(2 * p)     * step;
            float d1 = dist - (float)(2 * p + 1) * step;
            float2 v;
            v.x = __expf(coeff * d0 * d0);
            v.y = __expf(coeff * d1 * d1);
            edge_embs2[e * (N_GAUSS / 2) + p] = v;
        }
    }
}

// ---------------------------------------------------------------------------
// Launch
// Inputs (metadata order = reference signature order):
//   0: atomic_ns        int32   [N_NODES]
//   1: edge_index       int32   [2, N_EDGES]
//   2: coords           float32 [N_NODES, 3]
//   3: batch_node_vec   int32   [N_NODES]   (unused)
//   4: node_emb_weight  float32 [100, 128]
// Output (concatenated, float32): node_embs [N,128] | edge_embs [E,50] | edge_weights [E]
// ---------------------------------------------------------------------------
extern "C" void kernel_launch(void* const* d_in, const int* in_sizes, int n_in,
                              void* d_out, int out_size) {
    const int*   atomic_ns  = (const int*)d_in[0];
    const int*   edge_index = (const int*)d_in[1];
    const float* coords     = (const float*)d_in[2];
    const float* weight     = (const float*)d_in[4];

    const int       n_nodes = in_sizes[0];
    const long long n_edges = (long long)in_sizes[1] / 2;

    float* out = (float*)d_out;
    float*  out_node  = out;                                       // [N, 128]
    float*  out_eembs = out + (size_t)n_nodes * H_NF;              // [E, 50]
    float*  out_ew    = out_eembs + (size_t)n_edges * N_GAUSS;     // [E]

    // Node embedding gather: 32 threads per node
    {
        long long total_threads = (long long)n_nodes * 32;
        int tpb = 256;
        int blocks = (int)((total_threads + tpb - 1) / tpb);
        node_emb_kernel<<<blocks, tpb>>>(atomic_ns, (const float4*)weight,
                                         (float4*)out_node, n_nodes);
    }

    // Edge kernel
    {
        int blocks = (int)((n_edges + EPB - 1) / EPB);
        edge_kernel<<<blocks, TPB>>>(edge_index, coords,
                                     (float2*)out_eembs, out_ew, n_edges);
    }
}

// round 2
// speedup vs baseline: 1.5685x; 1.5685x over previous
#include <cuda_runtime.h>
#include <cuda_bf16.h>
#include <math.h>

// Problem constants
#define H_NF 128
#define N_GAUSS 50

#define EPB 256   // edges per block
#define TPB 256   // threads per block

// step = 10/49 ; coeff = -0.5/step^2
// exp(coeff*(d-o_p)^2) = 2^( coeff*log2e*(d-o_p)^2 ) = 2^( -(A*d - A*o_p)^2 )
// A = sqrt(-coeff*log2e) = sqrt(0.5*log2e)/step
#define LOG2E_D   1.4426950408889634
#define STEP_D    (10.0 / 49.0)
#define A_CONST   ((float)(0.8493255219056067 / STEP_D))   // sqrt(0.5*LOG2E)/step
#define AS_CONST  ((float)0.8493255219056067)              // A*step = sqrt(0.5*LOG2E)

__global__ __launch_bounds__(TPB) void fused_kernel(
    const int*   __restrict__ atomic_ns,   // [N]
    const int*   __restrict__ edge_index,  // [2, E]
    const float* __restrict__ coords,      // [N, 3]
    const float4* __restrict__ weight4,    // [100, 32] as float4
    float4* __restrict__ out_node4,        // [N, 32] as float4
    float2* __restrict__ out_eembs2,       // [E, 25] as float2
    float*  __restrict__ out_ew,           // [E]
    long long n_edges,
    int n_nodes,
    int edge_blocks)
{
    const int tid = threadIdx.x;

    // ---------------- node-embedding blocks ----------------
    if (blockIdx.x >= edge_blocks) {
        int nb   = blockIdx.x - edge_blocks;
        int node = nb * (TPB / 32) + (tid >> 5);
        int lane = tid & 31;
        if (node < n_nodes) {
            int a = __ldg(&atomic_ns[node]);
            float4 v = __ldg(&weight4[(size_t)a * 32 + lane]);
            __stcs(&out_node4[(size_t)node * 32 + lane], v);
        }
        return;
    }

    // ---------------- edge blocks ----------------
    __shared__ float s_dist[EPB];      // A * dist per edge
    __shared__ float s_voff[N_GAUSS];  // A * o_p

    const long long e0 = (long long)blockIdx.x * EPB;

    if (tid < N_GAUSS) s_voff[tid] = (float)tid * AS_CONST;

    const bool full = (e0 + EPB) <= n_edges;

    // Phase 1: one thread per edge -> distance
    {
        long long e = e0 + tid;
        if (full || e < n_edges) {
            int i = __ldg(&edge_index[e]);
            int j = __ldg(&edge_index[n_edges + e]);
            float ax = __ldg(&coords[(size_t)i * 3 + 0]);
            float ay = __ldg(&coords[(size_t)i * 3 + 1]);
            float az = __ldg(&coords[(size_t)i * 3 + 2]);
            float bx = __ldg(&coords[(size_t)j * 3 + 0]);
            float by = __ldg(&coords[(size_t)j * 3 + 1]);
            float bz = __ldg(&coords[(size_t)j * 3 + 2]);
            float dx = ax - bx, dy = ay - by, dz = az - bz;
            float dist = sqrtf(fmaf(dx, dx, fmaf(dy, dy, dz * dz)));
            __stcs(&out_ew[e], dist);
            s_dist[tid] = dist * A_CONST;
        }
    }
    __syncthreads();

    // Phase 2: gaussian smearing. EPB*25 = 6400 float2 per block.
    float2* __restrict__ base2 = out_eembs2 + e0 * (N_GAUSS / 2);

    if (full) {
        // exact: 6400 / 256 = 25 iterations, incremental (le, p) decode.
        int le = tid / 25;          // edge within block
        int p  = tid - le * 25;     // float2 pair index 0..24
        int idx = tid;              // flat float2 index within block
        #pragma unroll
        for (int it = 0; it < 25; ++it) {
            float u = s_dist[le];
            float2 v = *(const float2*)&s_voff[2 * p];
            float d0 = u - v.x;
            float d1 = u - v.y;
            float2 r;
            r.x = exp2f(d0 * -d0);
            r.y = exp2f(d1 * -d1);
            __stcs(&base2[idx], r);
            idx += TPB;
            // stride 256 = 10*25 + 6
            p += 6; le += 10;
            if (p >= 25) { p -= 25; le += 1; }
        }
    } else {
        // guarded tail block
        int rem = (int)(n_edges - e0);
        int total = rem * (N_GAUSS / 2);
        for (int k = tid; k < total; k += TPB) {
            int le = k / 25;
            int p  = k - le * 25;
            float u = s_dist[le];
            float2 v = *(const float2*)&s_voff[2 * p];
            float d0 = u - v.x;
            float d1 = u - v.y;
            float2 r;
            r.x = exp2f(d0 * -d0);
            r.y = exp2f(d1 * -d1);
            __stcs(&base2[k], r);
        }
    }
}

// ---------------------------------------------------------------------------
// Inputs (metadata order):
//   0: atomic_ns int32 [N], 1: edge_index int32 [2,E], 2: coords f32 [N,3],
//   3: batch_node_vec int32 [N] (unused), 4: node_emb_weight f32 [100,128]
// Output (f32): node_embs [N,128] | edge_embs [E,50] | edge_weights [E]
// ---------------------------------------------------------------------------
extern "C" void kernel_launch(void* const* d_in, const int* in_sizes, int n_in,
                              void* d_out, int out_size) {
    const int*   atomic_ns  = (const int*)d_in[0];
    const int*   edge_index = (const int*)d_in[1];
    const float* coords     = (const float*)d_in[2];
    const float* weight     = (const float*)d_in[4];

    const int       n_nodes = in_sizes[0];
    const long long n_edges = (long long)in_sizes[1] / 2;

    float* out = (float*)d_out;
    float* out_node  = out;
    float* out_eembs = out + (size_t)n_nodes * H_NF;
    float* out_ew    = out_eembs + (size_t)n_edges * N_GAUSS;

    int edge_blocks = (int)((n_edges + EPB - 1) / EPB);
    int node_blocks = (n_nodes + (TPB / 32) - 1) / (TPB / 32);

    fused_kernel<<<edge_blocks + node_blocks, TPB>>>(
        atomic_ns, edge_index, coords,
        (const float4*)weight,
        (float4*)out_node, (float2*)out_eembs, out_ew,
        n_edges, n_nodes, edge_blocks);
}

// round 3
// speedup vs baseline: 1.5973x; 1.0184x over previous
#include <cuda_runtime.h>
#include <cuda_bf16.h>
#include <math.h>

// Problem constants
#define H_NF 128
#define N_GAUSS 50

#define EPB 512   // edges per block (512*200B = 51200B flat, 16B-aligned)
#define TPB 256   // threads per block

// step = 10/49 ; coeff = -0.5/step^2
// exp(coeff*(d-o)^2) = 2^( -(A*d - A*o)^2 ),  A = sqrt(0.5*log2e)/step
#define STEP_D    (10.0 / 49.0)
#define A_CONST   ((float)(0.8493255219056067 / STEP_D))   // sqrt(0.5*log2e)/step
#define AS_CONST  ((float)0.8493255219056067)              // A*step

__global__ __launch_bounds__(TPB) void fused_kernel(
    const int*   __restrict__ atomic_ns,   // [N]
    const int*   __restrict__ edge_index,  // [2, E]
    const float* __restrict__ coords,      // [N, 3]
    const float4* __restrict__ weight4,    // [100, 32] as float4
    float4* __restrict__ out_node4,        // [N, 32] as float4
    float*  __restrict__ out_eembs,        // [E, 50]
    float*  __restrict__ out_ew,           // [E]
    long long n_edges,
    int n_nodes,
    int edge_blocks)
{
    const int tid = threadIdx.x;

    // ---------------- node-embedding blocks ----------------
    if (blockIdx.x >= edge_blocks) {
        int nb   = blockIdx.x - edge_blocks;
        int node = nb * (TPB / 32) + (tid >> 5);
        int lane = tid & 31;
        if (node < n_nodes) {
            int a = __ldg(&atomic_ns[node]);
            float4 v = __ldg(&weight4[(size_t)a * 32 + lane]);
            __stcs(&out_node4[(size_t)node * 32 + lane], v);
        }
        return;
    }

    // ---------------- edge blocks ----------------
    __shared__ float s_dist[EPB + 8];   // A * dist per edge (+pad for le+1 read)

    const long long e0 = (long long)blockIdx.x * EPB;
    const bool full = (e0 + EPB) <= n_edges;

    if (tid < 8) s_dist[EPB + tid] = 0.0f;

    // Phase 1: distances (2 edges per thread)
    #pragma unroll
    for (int s = 0; s < EPB / TPB; ++s) {
        long long e = e0 + tid + s * TPB;
        if (full || e < n_edges) {
            int i = __ldg(&edge_index[e]);
            int j = __ldg(&edge_index[n_edges + e]);
            float ax = __ldg(&coords[(size_t)i * 3 + 0]);
            float ay = __ldg(&coords[(size_t)i * 3 + 1]);
            float az = __ldg(&coords[(size_t)i * 3 + 2]);
            float bx = __ldg(&coords[(size_t)j * 3 + 0]);
            float by = __ldg(&coords[(size_t)j * 3 + 1]);
            float bz = __ldg(&coords[(size_t)j * 3 + 2]);
            float dx = ax - bx, dy = ay - by, dz = az - bz;
            float dist = sqrtf(fmaf(dx, dx, fmaf(dy, dy, dz * dz)));
            __stcs(&out_ew[e], dist);
            s_dist[tid + s * TPB] = dist * A_CONST;
        }
    }
    __syncthreads();

    // Phase 2: gaussian smearing as flat float4 stores.
    // Block region: EPB*50 = 25600 floats = 6400 float4 = 25 per thread.
    if (full) {
        float4* __restrict__ base4 =
            reinterpret_cast<float4*>(out_eembs + e0 * N_GAUSS);
        int f  = 4 * tid;          // flat float index
        int le = f / 50;           // edge within block
        int g  = f - 50 * le;      // gaussian index of lane .x (even)
        #pragma unroll
        for (int it = 0; it < 25; ++it) {
            float u  = s_dist[le];
            float un = s_dist[le + 1];
            bool span = (g == 48);             // elems 48,49 | next 0,1
            float og = (float)g * AS_CONST;    // exact, no accumulation drift
            float d0 = u - og;
            float d1 = d0 - AS_CONST;
            float d2 = span ? un : (d1 - AS_CONST);
            float d3 = d2 - AS_CONST;
            float4 r;
            r.x = exp2f(d0 * -d0);
            r.y = exp2f(d1 * -d1);
            r.z = exp2f(d2 * -d2);
            r.w = exp2f(d3 * -d3);
            __stcs(&base4[tid + it * TPB], r);
            // advance flat index by 4*TPB = 1024 floats: +20 edges, +24 gauss
            g += 24; le += 20;
            if (g >= 50) { g -= 50; le += 1; }
        }
    } else {
        // guarded tail block: float2 path
        int rem = (int)(n_edges - e0);
        int total = rem * (N_GAUSS / 2);
        float2* __restrict__ base2 =
            reinterpret_cast<float2*>(out_eembs + e0 * N_GAUSS);
        for (int k = tid; k < total; k += TPB) {
            int le = k / 25;
            int p  = k - le * 25;
            float u  = s_dist[le];
            float o0 = (float)(2 * p) * AS_CONST;
            float d0 = u - o0;
            float d1 = d0 - AS_CONST;
            float2 r;
            r.x = exp2f(d0 * -d0);
            r.y = exp2f(d1 * -d1);
            __stcs(&base2[k], r);
        }
    }
}

// ---------------------------------------------------------------------------
// Inputs (metadata order):
//   0: atomic_ns int32 [N], 1: edge_index int32 [2,E], 2: coords f32 [N,3],
//   3: batch_node_vec int32 [N] (unused), 4: node_emb_weight f32 [100,128]
// Output (f32): node_embs [N,128] | edge_embs [E,50] | edge_weights [E]
// ---------------------------------------------------------------------------
extern "C" void kernel_launch(void* const* d_in, const int* in_sizes, int n_in,
                              void* d_out, int out_size) {
    const int*   atomic_ns  = (const int*)d_in[0];
    const int*   edge_index = (const int*)d_in[1];
    const float* coords     = (const float*)d_in[2];
    const float* weight     = (const float*)d_in[4];

    const int       n_nodes = in_sizes[0];
    const long long n_edges = (long long)in_sizes[1] / 2;

    float* out = (float*)d_out;
    float* out_node  = out;
    float* out_eembs = out + (size_t)n_nodes * H_NF;
    float* out_ew    = out_eembs + (size_t)n_edges * N_GAUSS;

    int edge_blocks = (int)((n_edges + EPB - 1) / EPB);
    int node_blocks = (n_nodes + (TPB / 32) - 1) / (TPB / 32);

    fused_kernel<<<edge_blocks + node_blocks, TPB>>>(
        atomic_ns, edge_index, coords,
        (const float4*)weight,
        (float4*)out_node, out_eembs, out_ew,
        n_edges, n_nodes, edge_blocks);
}

// round 4
// speedup vs baseline: 1.6597x; 1.0391x over previous
#include <cuda_runtime.h>
#include <cuda_bf16.h>
#include <math.h>

// Problem constants
#define H_NF 128
#define N_GAUSS 50
#define MAX_NODES 100000

#define EPB 512   // edges per block (512*200B flat, 16B-aligned)
#define TPB 256   // threads per block

// step = 10/49 ; exp(coeff*(d-o)^2) = 2^( -(A*d - A*o)^2 ), A = sqrt(0.5*log2e)/step
#define STEP_D    (10.0 / 49.0)
#define A_CONST   ((float)(0.8493255219056067 / STEP_D))
#define AS_CONST  ((float)0.8493255219056067)

// Padded coords scratch: [N] float4 (xyz + pad). Static device array (no alloc).
__device__ float4 g_coords4[MAX_NODES];

// ---------------------------------------------------------------------------
// Prologue: pad coords [N,3] -> float4 [N]
// ---------------------------------------------------------------------------
__global__ void pad_coords_kernel(const float* __restrict__ coords, int n_nodes) {
    int i = blockIdx.x * blockDim.x + threadIdx.x;
    if (i < n_nodes) {
        float4 v;
        v.x = __ldg(&coords[(size_t)i * 3 + 0]);
        v.y = __ldg(&coords[(size_t)i * 3 + 1]);
        v.z = __ldg(&coords[(size_t)i * 3 + 2]);
        v.w = 0.0f;
        g_coords4[i] = v;
    }
}

// ---------------------------------------------------------------------------
// Fused: node-embedding gather blocks + edge blocks
// ---------------------------------------------------------------------------
__global__ __launch_bounds__(TPB) void fused_kernel(
    const int*   __restrict__ atomic_ns,   // [N]
    const int*   __restrict__ edge_index,  // [2, E]
    const float4* __restrict__ weight4,    // [100, 32] as float4
    float4* __restrict__ out_node4,        // [N, 32] as float4
    float*  __restrict__ out_eembs,        // [E, 50]
    float*  __restrict__ out_ew,           // [E]
    long long n_edges,
    int n_nodes,
    int edge_blocks)
{
    const int tid = threadIdx.x;

    // ---------------- node-embedding blocks ----------------
    if (blockIdx.x >= edge_blocks) {
        int nb   = blockIdx.x - edge_blocks;
        int node = nb * (TPB / 32) + (tid >> 5);
        int lane = tid & 31;
        if (node < n_nodes) {
            int a = __ldg(&atomic_ns[node]);
            float4 v = __ldg(&weight4[(size_t)a * 32 + lane]);
            __stcs(&out_node4[(size_t)node * 32 + lane], v);
        }
        return;
    }

    // ---------------- edge blocks ----------------
    __shared__ float s_dist[EPB + 8];

    const long long e0 = (long long)blockIdx.x * EPB;
    const bool full = (e0 + EPB) <= n_edges;

    if (tid < 8) s_dist[EPB + tid] = 0.0f;

    // Phase 1: distances (2 edges per thread), gathers via padded float4
    #pragma unroll
    for (int s = 0; s < EPB / TPB; ++s) {
        long long e = e0 + tid + s * TPB;
        if (full || e < n_edges) {
            int i = __ldg(&edge_index[e]);
            int j = __ldg(&edge_index[n_edges + e]);
            float4 a = __ldg(&g_coords4[i]);
            float4 b = __ldg(&g_coords4[j]);
            float dx = a.x - b.x, dy = a.y - b.y, dz = a.z - b.z;
            float dist = sqrtf(fmaf(dx, dx, fmaf(dy, dy, dz * dz)));
            __stcs(&out_ew[e], dist);
            s_dist[tid + s * TPB] = dist * A_CONST;
        }
    }
    __syncthreads();

    // Phase 2: gaussian smearing as flat float4 stores.
    if (full) {
        float4* __restrict__ base4 =
            reinterpret_cast<float4*>(out_eembs + e0 * N_GAUSS);
        int f  = 4 * tid;
        int le = f / 50;
        int g  = f - 50 * le;
        #pragma unroll
        for (int it = 0; it < 25; ++it) {
            float u  = s_dist[le];
            float un = s_dist[le + 1];
            bool span = (g == 48);
            float og = (float)g * AS_CONST;
            float d0 = u - og;
            float d1 = d0 - AS_CONST;
            float d2 = span ? un : (d1 - AS_CONST);
            float d3 = d2 - AS_CONST;
            float4 r;
            r.x = exp2f(d0 * -d0);
            r.y = exp2f(d1 * -d1);
            r.z = exp2f(d2 * -d2);
            r.w = exp2f(d3 * -d3);
            __stcs(&base4[tid + it * TPB], r);
            g += 24; le += 20;
            if (g >= 50) { g -= 50; le += 1; }
        }
    } else {
        int rem = (int)(n_edges - e0);
        int total = rem * (N_GAUSS / 2);
        float2* __restrict__ base2 =
            reinterpret_cast<float2*>(out_eembs + e0 * N_GAUSS);
        for (int k = tid; k < total; k += TPB) {
            int le = k / 25;
            int p  = k - le * 25;
            float u  = s_dist[le];
            float o0 = (float)(2 * p) * AS_CONST;
            float d0 = u - o0;
            float d1 = d0 - AS_CONST;
            float2 r;
            r.x = exp2f(d0 * -d0);
            r.y = exp2f(d1 * -d1);
            __stcs(&base2[k], r);
        }
    }
}

// ---------------------------------------------------------------------------
// Inputs (metadata order):
//   0: atomic_ns int32 [N], 1: edge_index int32 [2,E], 2: coords f32 [N,3],
//   3: batch_node_vec int32 [N] (unused), 4: node_emb_weight f32 [100,128]
// Output (f32): node_embs [N,128] | edge_embs [E,50] | edge_weights [E]
// ---------------------------------------------------------------------------
extern "C" void kernel_launch(void* const* d_in, const int* in_sizes, int n_in,
                              void* d_out, int out_size) {
    const int*   atomic_ns  = (const int*)d_in[0];
    const int*   edge_index = (const int*)d_in[1];
    const float* coords     = (const float*)d_in[2];
    const float* weight     = (const float*)d_in[4];

    const int       n_nodes = in_sizes[0];
    const long long n_edges = (long long)in_sizes[1] / 2;

    float* out = (float*)d_out;
    float* out_node  = out;
    float* out_eembs = out + (size_t)n_nodes * H_NF;
    float* out_ew    = out_eembs + (size_t)n_edges * N_GAUSS;

    // Prologue: pad coords into float4 scratch
    {
        int tpb = 256;
        int blocks = (n_nodes + tpb - 1) / tpb;
        pad_coords_kernel<<<blocks, tpb>>>(coords, n_nodes);
    }

    int edge_blocks = (int)((n_edges + EPB - 1) / EPB);
    int node_blocks = (n_nodes + (TPB / 32) - 1) / (TPB / 32);

    fused_kernel<<<edge_blocks + node_blocks, TPB>>>(
        atomic_ns, edge_index,
        (const float4*)weight,
        (float4*)out_node, out_eembs, out_ew,
        n_edges, n_nodes, edge_blocks);
}

// round 5
// speedup vs baseline: 1.6617x; 1.0012x over previous
#include <cuda_runtime.h>
#include <cuda_bf16.h>
#include <math.h>

// Problem constants
#define H_NF 128
#define N_GAUSS 50
#define MAX_NODES 100000

#define EPB 512   // edges per block (512*200B flat, 16B-aligned)
#define TPB 256   // threads per block

// step = 10/49 ; exp(coeff*(d-o)^2) = 2^( -(A*d - A*o)^2 ), A = sqrt(0.5*log2e)/step
#define STEP_D    (10.0 / 49.0)
#define A_CONST   ((float)(0.8493255219056067 / STEP_D))
#define AS_CONST  ((float)0.8493255219056067)

// Padded coords scratch: [N] float4 (xyz + pad). Static device array (no alloc).
__device__ float4 g_coords4[MAX_NODES];

// ---------------------------------------------------------------------------
// Prologue: pad coords [N,3] -> float4 [N]
// ---------------------------------------------------------------------------
__global__ void pad_coords_kernel(const float* __restrict__ coords, int n_nodes) {
    int i = blockIdx.x * blockDim.x + threadIdx.x;
    if (i < n_nodes) {
        float4 v;
        v.x = __ldg(&coords[(size_t)i * 3 + 0]);
        v.y = __ldg(&coords[(size_t)i * 3 + 1]);
        v.z = __ldg(&coords[(size_t)i * 3 + 2]);
        v.w = 0.0f;
        g_coords4[i] = v;
    }
}

// ---------------------------------------------------------------------------
// Fused: node-embedding gather blocks + edge blocks
// ---------------------------------------------------------------------------
__global__ __launch_bounds__(TPB) void fused_kernel(
    const int*   __restrict__ atomic_ns,   // [N]
    const int*   __restrict__ edge_index,  // [2, E]
    const float4* __restrict__ weight4,    // [100, 32] as float4
    float4* __restrict__ out_node4,        // [N, 32] as float4
    float*  __restrict__ out_eembs,        // [E, 50]
    float*  __restrict__ out_ew,           // [E]
    long long n_edges,
    int n_nodes,
    int edge_blocks)
{
    const int tid = threadIdx.x;

    // ---------------- node-embedding blocks ----------------
    if (blockIdx.x >= edge_blocks) {
        int nb   = blockIdx.x - edge_blocks;
        int node = nb * (TPB / 32) + (tid >> 5);
        int lane = tid & 31;
        if (node < n_nodes) {
            int a = __ldg(&atomic_ns[node]);
            float4 v = __ldg(&weight4[(size_t)a * 32 + lane]);
            __stcs(&out_node4[(size_t)node * 32 + lane], v);
        }
        return;
    }

    // ---------------- edge blocks ----------------
    __shared__ float s_dist[EPB + 8];

    const long long e0 = (long long)blockIdx.x * EPB;
    const bool full = (e0 + EPB) <= n_edges;

    // Phase 1: distances (2 edges per thread), batched loads for MLP=4
    if (full) {
        long long eA = e0 + tid;
        long long eB = eA + TPB;
        int iA = __ldcg(&edge_index[eA]);
        int jA = __ldcg(&edge_index[n_edges + eA]);
        int iB = __ldcg(&edge_index[eB]);
        int jB = __ldcg(&edge_index[n_edges + eB]);
        float4 a0 = __ldcg(&g_coords4[iA]);
        float4 b0 = __ldcg(&g_coords4[jA]);
        float4 a1 = __ldcg(&g_coords4[iB]);
        float4 b1 = __ldcg(&g_coords4[jB]);
        float dx0 = a0.x - b0.x, dy0 = a0.y - b0.y, dz0 = a0.z - b0.z;
        float dx1 = a1.x - b1.x, dy1 = a1.y - b1.y, dz1 = a1.z - b1.z;
        float dist0 = sqrtf(fmaf(dx0, dx0, fmaf(dy0, dy0, dz0 * dz0)));
        float dist1 = sqrtf(fmaf(dx1, dx1, fmaf(dy1, dy1, dz1 * dz1)));
        __stcs(&out_ew[eA], dist0);
        __stcs(&out_ew[eB], dist1);
        s_dist[tid]       = dist0 * A_CONST;
        s_dist[tid + TPB] = dist1 * A_CONST;
    } else {
        if (tid < 8) s_dist[EPB + tid] = 0.0f;
        #pragma unroll
        for (int s = 0; s < EPB / TPB; ++s) {
            long long e = e0 + tid + s * TPB;
            if (e < n_edges) {
                int i = __ldcg(&edge_index[e]);
                int j = __ldcg(&edge_index[n_edges + e]);
                float4 a = __ldcg(&g_coords4[i]);
                float4 b = __ldcg(&g_coords4[j]);
                float dx = a.x - b.x, dy = a.y - b.y, dz = a.z - b.z;
                float dist = sqrtf(fmaf(dx, dx, fmaf(dy, dy, dz * dz)));
                __stcs(&out_ew[e], dist);
                s_dist[tid + s * TPB] = dist * A_CONST;
            } else {
                s_dist[tid + s * TPB] = 0.0f;
            }
        }
    }
    __syncthreads();

    // Phase 2: gaussian smearing as flat float4 stores.
    if (full) {
        float4* __restrict__ base4 =
            reinterpret_cast<float4*>(out_eembs + e0 * N_GAUSS);
        int f  = 4 * tid;
        int le = f / 50;
        int g  = f - 50 * le;
        #pragma unroll
        for (int it = 0; it < 25; ++it) {
            float u  = s_dist[le];
            bool span = (g == 48);
            float un = 0.0f;
            if (span) un = s_dist[le + 1];   // predicated: 1-in-25 iters
            float og = (float)g * AS_CONST;
            float d0 = u - og;
            float d1 = d0 - AS_CONST;
            float d2 = span ? un : (d1 - AS_CONST);
            float d3 = d2 - AS_CONST;
            float4 r;
            r.x = exp2f(d0 * -d0);
            r.y = exp2f(d1 * -d1);
            r.z = exp2f(d2 * -d2);
            r.w = exp2f(d3 * -d3);
            __stcs(&base4[tid + it * TPB], r);
            g += 24; le += 20;
            if (g >= 50) { g -= 50; le += 1; }
        }
    } else {
        int rem = (int)(n_edges - e0);
        int total = rem * (N_GAUSS / 2);
        float2* __restrict__ base2 =
            reinterpret_cast<float2*>(out_eembs + e0 * N_GAUSS);
        for (int k = tid; k < total; k += TPB) {
            int le = k / 25;
            int p  = k - le * 25;
            float u  = s_dist[le];
            float o0 = (float)(2 * p) * AS_CONST;
            float d0 = u - o0;
            float d1 = d0 - AS_CONST;
            float2 r;
            r.x = exp2f(d0 * -d0);
            r.y = exp2f(d1 * -d1);
            __stcs(&base2[k], r);
        }
    }
}

// ---------------------------------------------------------------------------
// Inputs (metadata order):
//   0: atomic_ns int32 [N], 1: edge_index int32 [2,E], 2: coords f32 [N,3],
//   3: batch_node_vec int32 [N] (unused), 4: node_emb_weight f32 [100,128]
// Output (f32): node_embs [N,128] | edge_embs [E,50] | edge_weights [E]
// ---------------------------------------------------------------------------
extern "C" void kernel_launch(void* const* d_in, const int* in_sizes, int n_in,
                              void* d_out, int out_size) {
    const int*   atomic_ns  = (const int*)d_in[0];
    const int*   edge_index = (const int*)d_in[1];
    const float* coords     = (const float*)d_in[2];
    const float* weight     = (const float*)d_in[4];

    const int       n_nodes = in_sizes[0];
    const long long n_edges = (long long)in_sizes[1] / 2;

    float* out = (float*)d_out;
    float* out_node  = out;
    float* out_eembs = out + (size_t)n_nodes * H_NF;
    float* out_ew    = out_eembs + (size_t)n_edges * N_GAUSS;

    // Prologue: pad coords into float4 scratch
    {
        int tpb = 256;
        int blocks = (n_nodes + tpb - 1) / tpb;
        pad_coords_kernel<<<blocks, tpb>>>(coords, n_nodes);
    }

    int edge_blocks = (int)((n_edges + EPB - 1) / EPB);
    int node_blocks = (n_nodes + (TPB / 32) - 1) / (TPB / 32);

    fused_kernel<<<edge_blocks + node_blocks, TPB>>>(
        atomic_ns, edge_index,
        (const float4*)weight,
        (float4*)out_node, out_eembs, out_ew,
        n_edges, n_nodes, edge_blocks);
}

// round 6
// speedup vs baseline: 1.6646x; 1.0018x over previous
#include <cuda_runtime.h>
#include <cuda_bf16.h>
#include <math.h>

// Problem constants
#define H_NF 128
#define N_GAUSS 50
#define MAX_NODES 100000

#define EPB 512   // edges per block
#define TPB 256   // threads per block
#define EPW 64    // edges per warp (512 / 8 warps)

// step = 10/49 ; exp(coeff*(d-o)^2) = 2^( -(A*d - A*o)^2 ), A = sqrt(0.5*log2e)/step
#define STEP_D    (10.0 / 49.0)
#define A_CONST   ((float)(0.8493255219056067 / STEP_D))
#define AS_CONST  ((float)0.8493255219056067)

// Padded coords scratch: [N] float4. Static device array (no alloc).
__device__ float4 g_coords4[MAX_NODES];

// ---------------------------------------------------------------------------
// Prologue: pad coords [N,3] -> float4 [N]
// ---------------------------------------------------------------------------
__global__ void pad_coords_kernel(const float* __restrict__ coords, int n_nodes) {
    int i = blockIdx.x * blockDim.x + threadIdx.x;
    if (i < n_nodes) {
        float4 v;
        v.x = __ldg(&coords[(size_t)i * 3 + 0]);
        v.y = __ldg(&coords[(size_t)i * 3 + 1]);
        v.z = __ldg(&coords[(size_t)i * 3 + 2]);
        v.w = 0.0f;
        g_coords4[i] = v;
    }
}

// ---------------------------------------------------------------------------
// Fused: node-embedding gather blocks + edge blocks (warp-local pipeline)
// ---------------------------------------------------------------------------
__global__ __launch_bounds__(TPB) void fused_kernel(
    const int*   __restrict__ atomic_ns,   // [N]
    const int*   __restrict__ edge_index,  // [2, E]
    const float4* __restrict__ weight4,    // [100, 32] as float4
    float4* __restrict__ out_node4,        // [N, 32] as float4
    float*  __restrict__ out_eembs,        // [E, 50]
    float*  __restrict__ out_ew,           // [E]
    long long n_edges,
    int n_nodes,
    int edge_blocks)
{
    const int tid = threadIdx.x;

    // ---------------- node-embedding blocks ----------------
    if (blockIdx.x >= edge_blocks) {
        int nb   = blockIdx.x - edge_blocks;
        int node = nb * (TPB / 32) + (tid >> 5);
        int lane = tid & 31;
        if (node < n_nodes) {
            int a = __ldg(&atomic_ns[node]);
            float4 v = __ldg(&weight4[(size_t)a * 32 + lane]);
            __stcs(&out_node4[(size_t)node * 32 + lane], v);
        }
        return;
    }

    // ---------------- edge blocks ----------------
    __shared__ float s_dist[EPB + 8];

    const long long e0 = (long long)blockIdx.x * EPB;
    const bool full = (e0 + EPB) <= n_edges;

    if (full) {
        // Warp-local pipeline: no block barrier. Warp w owns 64 edges.
        const int w    = tid >> 5;
        const int lane = tid & 31;
        float* s_seg = s_dist + w * EPW;
        const long long we0 = e0 + (long long)w * EPW;

        // Phase 1 (warp): gather + distance for edges [we0, we0+64)
        {
            long long eA = we0 + lane;
            long long eB = eA + 32;
            int iA = __ldcg(&edge_index[eA]);
            int jA = __ldcg(&edge_index[n_edges + eA]);
            int iB = __ldcg(&edge_index[eB]);
            int jB = __ldcg(&edge_index[n_edges + eB]);
            float4 a0 = __ldcg(&g_coords4[iA]);
            float4 b0 = __ldcg(&g_coords4[jA]);
            float4 a1 = __ldcg(&g_coords4[iB]);
            float4 b1 = __ldcg(&g_coords4[jB]);
            float dx0 = a0.x - b0.x, dy0 = a0.y - b0.y, dz0 = a0.z - b0.z;
            float dx1 = a1.x - b1.x, dy1 = a1.y - b1.y, dz1 = a1.z - b1.z;
            float dist0 = sqrtf(fmaf(dx0, dx0, fmaf(dy0, dy0, dz0 * dz0)));
            float dist1 = sqrtf(fmaf(dx1, dx1, fmaf(dy1, dy1, dz1 * dz1)));
            __stcs(&out_ew[eA], dist0);
            __stcs(&out_ew[eB], dist1);
            s_seg[lane]      = dist0 * A_CONST;
            s_seg[lane + 32] = dist1 * A_CONST;
        }
        __syncwarp();

        // Phase 2 (warp): 64 edges * 50 floats = 800 float4, 25 per lane.
        float4* __restrict__ base4 =
            reinterpret_cast<float4*>(out_eembs + we0 * N_GAUSS);
        int f  = 4 * lane;
        int le = f / 50;            // 0..63 within warp segment
        int g  = f - 50 * le;
        #pragma unroll
        for (int it = 0; it < 25; ++it) {
            float u  = s_seg[le];
            bool span = (g == 48);
            float un = 0.0f;
            if (span) un = s_seg[le + 1];   // never crosses segment (proof in notes)
            float og = (float)g * AS_CONST;
            float d0 = u - og;
            float d1 = d0 - AS_CONST;
            float d2 = span ? un : (d1 - AS_CONST);
            float d3 = d2 - AS_CONST;
            float4 r;
            r.x = exp2f(d0 * -d0);
            r.y = exp2f(d1 * -d1);
            r.z = exp2f(d2 * -d2);
            r.w = exp2f(d3 * -d3);
            __stcs(&base4[lane + it * 32], r);
            // advance flat float index by 128: +2 edges, +28 gauss
            g += 28; le += 2;
            if (g >= 50) { g -= 50; le += 1; }
        }
    } else {
        // Guarded tail block (rare): block-wide with barrier.
        if (tid < 8) s_dist[EPB + tid] = 0.0f;
        #pragma unroll
        for (int s = 0; s < EPB / TPB; ++s) {
            long long e = e0 + tid + s * TPB;
            if (e < n_edges) {
                int i = __ldcg(&edge_index[e]);
                int j = __ldcg(&edge_index[n_edges + e]);
                float4 a = __ldcg(&g_coords4[i]);
                float4 b = __ldcg(&g_coords4[j]);
                float dx = a.x - b.x, dy = a.y - b.y, dz = a.z - b.z;
                float dist = sqrtf(fmaf(dx, dx, fmaf(dy, dy, dz * dz)));
                __stcs(&out_ew[e], dist);
                s_dist[tid + s * TPB] = dist * A_CONST;
            } else {
                s_dist[tid + s * TPB] = 0.0f;
            }
        }
        __syncthreads();
        int rem = (int)(n_edges - e0);
        int total = rem * (N_GAUSS / 2);
        float2* __restrict__ base2 =
            reinterpret_cast<float2*>(out_eembs + e0 * N_GAUSS);
        for (int k = tid; k < total; k += TPB) {
            int le = k / 25;
            int p  = k - le * 25;
            float u  = s_dist[le];
            float o0 = (float)(2 * p) * AS_CONST;
            float d0 = u - o0;
            float d1 = d0 - AS_CONST;
            float2 r;
            r.x = exp2f(d0 * -d0);
            r.y = exp2f(d1 * -d1);
            __stcs(&base2[k], r);
        }
    }
}

// ---------------------------------------------------------------------------
// Inputs (metadata order):
//   0: atomic_ns int32 [N], 1: edge_index int32 [2,E], 2: coords f32 [N,3],
//   3: batch_node_vec int32 [N] (unused), 4: node_emb_weight f32 [100,128]
// Output (f32): node_embs [N,128] | edge_embs [E,50] | edge_weights [E]
// ---------------------------------------------------------------------------
extern "C" void kernel_launch(void* const* d_in, const int* in_sizes, int n_in,
                              void* d_out, int out_size) {
    const int*   atomic_ns  = (const int*)d_in[0];
    const int*   edge_index = (const int*)d_in[1];
    const float* coords     = (const float*)d_in[2];
    const float* weight     = (const float*)d_in[4];

    const int       n_nodes = in_sizes[0];
    const long long n_edges = (long long)in_sizes[1] / 2;

    float* out = (float*)d_out;
    float* out_node  = out;
    float* out_eembs = out + (size_t)n_nodes * H_NF;
    float* out_ew    = out_eembs + (size_t)n_edges * N_GAUSS;

    // Prologue: pad coords into float4 scratch
    {
        int tpb = 256;
        int blocks = (n_nodes + tpb - 1) / tpb;
        pad_coords_kernel<<<blocks, tpb>>>(coords, n_nodes);
    }

    int edge_blocks = (int)((n_edges + EPB - 1) / EPB);
    int node_blocks = (n_nodes + (TPB / 32) - 1) / (TPB / 32);

    fused_kernel<<<edge_blocks + node_blocks, TPB>>>(
        atomic_ns, edge_index,
        (const float4*)weight,
        (float4*)out_node, out_eembs, out_ew,
        n_edges, n_nodes, edge_blocks);
}